// round 11
// baseline (speedup 1.0000x reference)
#include <cuda_runtime.h>
#include <cuda_bf16.h>

#define S_LEN 2048
#define B_DIM 32
#define H_DIM 1024
#define M_TOT (S_LEN * B_DIM)

// ---------------- scratch ----------------
__device__ char g_enc_a1[(size_t)M_TOT * H_DIM];   // 64 MB, enc hi limb (q=2^-4)
__device__ char g_enc_a0[(size_t)M_TOT * H_DIM];   // 64 MB, enc lo limb (q=2^-12)
__device__ char g_w2_b1[H_DIM * H_DIM];            // 1 MB (q=2^-9)
__device__ char g_w2_b0[H_DIM * H_DIM];            // 1 MB (q=2^-17)
__device__ float g_t1[B_DIM * H_DIM];
__device__ float g_scores[B_DIM * S_LEN];

// ---------------- helpers ----------------
__device__ __forceinline__ unsigned smem_u32(const void* p) {
    unsigned a;
    asm("{ .reg .u64 t; cvta.to.shared.u64 t, %1; cvt.u32.u64 %0, t; }" : "=r"(a) : "l"(p));
    return a;
}
__device__ __forceinline__ uint4 ldsm_x4(unsigned addr) {
    uint4 r;
    asm volatile("ldmatrix.sync.aligned.m8n8.x4.shared.b16 {%0,%1,%2,%3}, [%4];"
                 : "=r"(r.x), "=r"(r.y), "=r"(r.z), "=r"(r.w) : "r"(addr));
    return r;
}
__device__ __forceinline__ void mma_s8(int* c, uint4 a, unsigned b0, unsigned b1) {
    asm volatile(
        "mma.sync.aligned.m16n8k32.row.col.s32.s8.s8.s32 "
        "{%0,%1,%2,%3}, {%4,%5,%6,%7}, {%8,%9}, {%0,%1,%2,%3};"
        : "+r"(c[0]), "+r"(c[1]), "+r"(c[2]), "+r"(c[3])
        : "r"(a.x), "r"(a.y), "r"(a.z), "r"(a.w), "r"(b0), "r"(b1));
}
__device__ __forceinline__ void cp_async16(unsigned sdst, const void* gsrc) {
    unsigned long long g;
    asm("cvta.to.global.u64 %0, %1;" : "=l"(g) : "l"(gsrc));
    asm volatile("cp.async.cg.shared.global [%0], [%1], 16;" :: "r"(sdst), "l"(g) : "memory");
}
#define CP_COMMIT() asm volatile("cp.async.commit_group;" ::: "memory")
#define CP_WAIT0()  asm volatile("cp.async.wait_group 0;" ::: "memory")
#define CP_WAIT1()  asm volatile("cp.async.wait_group 1;" ::: "memory")

__device__ __forceinline__ int q8(float x, float s) {
    int q = __float2int_rn(x * s);
    return max(-127, min(127, q));
}
__device__ __forceinline__ unsigned pack4(int a, int b, int c, int d) {
    return (unsigned)(a & 0xff) | ((unsigned)(b & 0xff) << 8) |
           ((unsigned)(c & 0xff) << 16) | ((unsigned)(d & 0xff) << 24);
}

// rational tanh, 4 at a time, one Newton-refined RCP
__device__ __forceinline__ void tanh4(const float* x, float* y) {
    float al[4], be[4];
#pragma unroll
    for (int i = 0; i < 4; i++) {
        float xc = fminf(fmaxf(x[i], -7.90531110763549805f), 7.90531110763549805f);
        float t = xc * xc;
        float a = -2.76076847742355e-16f;
        a = fmaf(a, t, 2.00018790482477e-13f);
        a = fmaf(a, t, -8.60467152213735e-11f);
        a = fmaf(a, t, 5.12229709037114e-08f);
        a = fmaf(a, t, 1.48572235717979e-05f);
        a = fmaf(a, t, 6.37261928875436e-04f);
        a = fmaf(a, t, 4.89352455891786e-03f);
        al[i] = xc * a;
        float b = 1.19825839466702e-06f;
        b = fmaf(b, t, 1.18534705686654e-04f);
        b = fmaf(b, t, 2.26843463243900e-03f);
        be[i] = fmaf(b, t, 4.89352518554385e-03f);
    }
    float p01 = be[0] * be[1];
    float p23 = be[2] * be[3];
    float p = p01 * p23;
    float r;
    asm("rcp.approx.f32 %0, %1;" : "=f"(r) : "f"(p));
    r = r * fmaf(-p, r, 2.0f);
    float q01 = r * p23, q23 = r * p01;
    y[0] = al[0] * (q01 * be[1]);
    y[1] = al[1] * (q01 * be[0]);
    y[2] = al[2] * (q23 * be[3]);
    y[3] = al[3] * (q23 * be[2]);
}

// ---------------- fused prep: enc int8 limbs + w2 limbs + t1 + init ----------------
#define PREP_ENC_BLKS   16384
#define PREP_W2_BLKS    1024
#define PREP_T1_BLKS    4096
#define PREP_INIT_BLKS  256
#define PREP_GRID (PREP_ENC_BLKS + PREP_W2_BLKS + PREP_T1_BLKS + PREP_INIT_BLKS)

__global__ void k_prep(const float4* __restrict__ enc4,
                       const float* __restrict__ attn_w,
                       const float* __restrict__ attn_b,
                       const float* __restrict__ hidden,
                       float* __restrict__ ctx) {
    int blk = blockIdx.x;
    int tid = threadIdx.x;
    if (blk < PREP_ENC_BLKS) {
        // 16 floats per thread -> 16 a1 bytes + 16 a0 bytes (STG.128 each)
        size_t i0 = ((size_t)blk * 256 + tid) * 4;     // float4 index
        float4 x[4];
#pragma unroll
        for (int i = 0; i < 4; i++) x[i] = enc4[i0 + i];
        unsigned p1[4], p0[4];
#pragma unroll
        for (int i = 0; i < 4; i++) {
            int ax = q8(x[i].x, 16.f), ay = q8(x[i].y, 16.f);
            int az = q8(x[i].z, 16.f), aw = q8(x[i].w, 16.f);
            int bx = q8(fmaf((float)ax, -0.0625f, x[i].x), 4096.f);
            int by = q8(fmaf((float)ay, -0.0625f, x[i].y), 4096.f);
            int bz = q8(fmaf((float)az, -0.0625f, x[i].z), 4096.f);
            int bw = q8(fmaf((float)aw, -0.0625f, x[i].w), 4096.f);
            p1[i] = pack4(ax, ay, az, aw);
            p0[i] = pack4(bx, by, bz, bw);
        }
        *(uint4*)(g_enc_a1 + i0 * 4) = make_uint4(p1[0], p1[1], p1[2], p1[3]);
        *(uint4*)(g_enc_a0 + i0 * 4) = make_uint4(p0[0], p0[1], p0[2], p0[3]);
    } else if (blk < PREP_ENC_BLKS + PREP_W2_BLKS) {
        int i = (blk - PREP_ENC_BLKS) * 256 + tid;     // float4 index in W2 (1024x1024)
        int row = i >> 8, c4 = i & 255;
        float4 x = *(const float4*)(attn_w + (size_t)row * (2 * H_DIM) + H_DIM + c4 * 4);
        int ax = q8(x.x, 512.f), ay = q8(x.y, 512.f);
        int az = q8(x.z, 512.f), aw = q8(x.w, 512.f);
        int bx = q8(fmaf((float)ax, -0.001953125f, x.x), 131072.f);
        int by = q8(fmaf((float)ay, -0.001953125f, x.y), 131072.f);
        int bz = q8(fmaf((float)az, -0.001953125f, x.z), 131072.f);
        int bw = q8(fmaf((float)aw, -0.001953125f, x.w), 131072.f);
        *(unsigned*)(g_w2_b1 + (size_t)i * 4) = pack4(ax, ay, az, aw);
        *(unsigned*)(g_w2_b0 + (size_t)i * 4) = pack4(bx, by, bz, bw);
    } else if (blk < PREP_ENC_BLKS + PREP_W2_BLKS + PREP_T1_BLKS) {
        int w = (blk - PREP_ENC_BLKS - PREP_W2_BLKS) * 8 + (tid >> 5);
        int lane = tid & 31;
        int b = w >> 10;
        int h = w & (H_DIM - 1);
        const float4* hp = (const float4*)(hidden + (size_t)b * H_DIM);
        const float4* wp = (const float4*)(attn_w + (size_t)h * 2 * H_DIM);
        float acc = 0.f;
#pragma unroll
        for (int i = 0; i < 8; i++) {
            int idx = i * 32 + lane;
            float4 hv = hp[idx];
            float4 wv = wp[idx];
            acc += hv.x * wv.x + hv.y * wv.y + hv.z * wv.z + hv.w * wv.w;
        }
#pragma unroll
        for (int off = 16; off; off >>= 1) acc += __shfl_down_sync(0xffffffffu, acc, off);
        if (lane == 0) g_t1[w] = acc + attn_b[h];
    } else {
        int i = (blk - PREP_ENC_BLKS - PREP_W2_BLKS - PREP_T1_BLKS) * 256 + tid;
        if (i < B_DIM * S_LEN) g_scores[i] = 0.f;
        if (i < B_DIM * H_DIM) ctx[i] = 0.f;
    }
}

// ---------------- K1: int8 2-limb GEMM, CTA 128x64, warp tile 64x32 ----------------
#define BM 128
#define BN 64
#define BK 32
// 48-byte rows (3 x 16B chunks): chunk index = row*3 + c, 3 coprime 8 -> conflict-free ldmatrix
#define A1_OFF 0
#define A0_OFF 6144
#define B1_OFF 12288
#define B0_OFF 15360
#define STAGE_B 18432
#define NSTAGE 3
#define VS_OFF  (NSTAGE * STAGE_B)          // 55296: 64 f32
#define SROW_OFF (VS_OFF + 256)             // 55552: 128 f32
#define K1_SMEM  (SROW_OFF + 512)           // 56064

#define W11 1.220703125e-4f                 // 2^-13
#define WMID 4.76837158203125e-7f           // 2^-21
#define W00 1.862645149230957e-9f           // 2^-29

__device__ __forceinline__ void fill_stage(unsigned sb, int m0, int n0, int kk, int tid) {
    {   // A: 128 rows x 32B, both limbs; thread = row
        size_t g = (size_t)(m0 + tid) * H_DIM + kk;
        unsigned s = (unsigned)tid * 48u;
        cp_async16(sb + A1_OFF + s,      g_enc_a1 + g);
        cp_async16(sb + A1_OFF + s + 16, g_enc_a1 + g + 16);
        cp_async16(sb + A0_OFF + s,      g_enc_a0 + g);
        cp_async16(sb + A0_OFF + s + 16, g_enc_a0 + g + 16);
    }
    {   // B: 64 rows x 32B, both limbs; thread -> (row, chunk)
        int row = tid >> 1, c = tid & 1;
        size_t g = (size_t)(n0 + row) * H_DIM + kk + c * 16;
        unsigned s = (unsigned)row * 48u + (unsigned)c * 16u;
        cp_async16(sb + B1_OFF + s, g_w2_b1 + g);
        cp_async16(sb + B0_OFF + s, g_w2_b0 + g);
    }
}

__global__ void __launch_bounds__(128, 2) k1_gemm(const float* __restrict__ v) {
    extern __shared__ char smem[];
    const unsigned sbase = smem_u32(smem);
    const int tid = threadIdx.x;
    const int wid = tid >> 5;
    const int L = tid & 31;
    const int wm = wid & 1;             // m half (64 rows)
    const int wn = wid >> 1;            // n half (32 cols)
    const int m0 = blockIdx.y * BM;
    const int n0 = blockIdx.x * BN;

    float* vs = (float*)(smem + VS_OFF);
    float* srow = (float*)(smem + SROW_OFF);
    if (tid < BN) vs[tid] = v[n0 + tid];
    srow[tid] = 0.f;

    fill_stage(sbase, m0, n0, 0, tid);
    CP_COMMIT();
    fill_stage(sbase + STAGE_B, m0, n0, BK, tid);
    CP_COMMIT();

    int s11[4][4][4], smid[4][4][4], s00[4][4][4];
#pragma unroll
    for (int i = 0; i < 4; i++)
#pragma unroll
        for (int j = 0; j < 4; j++)
#pragma unroll
            for (int e = 0; e < 4; e++) { s11[i][j][e] = 0; smid[i][j][e] = 0; s00[i][j][e] = 0; }

    // ldmatrix lane addressing (row, 16B-chunk) within tile
    const int a_r = wm * 64 + ((L >> 3) & 1) * 8 + (L & 7);   // + mf*16
    const int a_c = L >> 4;                                    // chunk 0/1
    const int b_r = wn * 32 + (L >> 4) * 8 + (L & 7);          // + j*16
    const int b_c = (L >> 3) & 1;

    const int NKT = H_DIM / BK;              // 32
    int slot = 0, nslot = 2;
    for (int kt = 0; kt < NKT; kt++) {
        if (kt + 1 < NKT) { CP_WAIT1(); } else { CP_WAIT0(); }
        __syncthreads();
        if (kt + 2 < NKT) {
            fill_stage(sbase + nslot * STAGE_B, m0, n0, (kt + 2) * BK, tid);
            CP_COMMIT();
        }
        const unsigned sb = sbase + slot * STAGE_B;

        uint4 bp1[2], bp0[2];
#pragma unroll
        for (int j = 0; j < 2; j++) {
            unsigned boff = (unsigned)(b_r + j * 16) * 48u + (unsigned)b_c * 16u;
            bp1[j] = ldsm_x4(sb + B1_OFF + boff);
            bp0[j] = ldsm_x4(sb + B0_OFF + boff);
        }
        {   // a1 limb pass
            uint4 a[4];
#pragma unroll
            for (int mf = 0; mf < 4; mf++) {
                unsigned aoff = (unsigned)(a_r + mf * 16) * 48u + (unsigned)a_c * 16u;
                a[mf] = ldsm_x4(sb + A1_OFF + aoff);
            }
#pragma unroll
            for (int j = 0; j < 2; j++)
#pragma unroll
                for (int mf = 0; mf < 4; mf++) {
                    mma_s8(s11[mf][j * 2],     a[mf], bp1[j].x, bp1[j].y);
                    mma_s8(s11[mf][j * 2 + 1], a[mf], bp1[j].z, bp1[j].w);
                }
#pragma unroll
            for (int j = 0; j < 2; j++)
#pragma unroll
                for (int mf = 0; mf < 4; mf++) {
                    mma_s8(smid[mf][j * 2],     a[mf], bp0[j].x, bp0[j].y);
                    mma_s8(smid[mf][j * 2 + 1], a[mf], bp0[j].z, bp0[j].w);
                }
        }
        {   // a0 limb pass
            uint4 a[4];
#pragma unroll
            for (int mf = 0; mf < 4; mf++) {
                unsigned aoff = (unsigned)(a_r + mf * 16) * 48u + (unsigned)a_c * 16u;
                a[mf] = ldsm_x4(sb + A0_OFF + aoff);
            }
#pragma unroll
            for (int j = 0; j < 2; j++)
#pragma unroll
                for (int mf = 0; mf < 4; mf++) {
                    mma_s8(smid[mf][j * 2],     a[mf], bp1[j].x, bp1[j].y);
                    mma_s8(smid[mf][j * 2 + 1], a[mf], bp1[j].z, bp1[j].w);
                }
#pragma unroll
            for (int j = 0; j < 2; j++)
#pragma unroll
                for (int mf = 0; mf < 4; mf++) {
                    mma_s8(s00[mf][j * 2],     a[mf], bp0[j].x, bp0[j].y);
                    mma_s8(s00[mf][j * 2 + 1], a[mf], bp0[j].z, bp0[j].w);
                }
        }
        slot = (slot == 2) ? 0 : slot + 1;
        nslot = (nslot == 2) ? 0 : nslot + 1;
    }

    // ---------------- epilogue: combine limbs + t1 + tanh + v-dot + row reduce ----------------
    const int q = L >> 2;
#pragma unroll
    for (int mf = 0; mf < 4; mf++) {
        const int r0 = m0 + wm * 64 + mf * 16 + q;
        const int bb0 = r0 & 31;
        const int bb1 = (r0 + 8) & 31;
        float2 t0a[4], t1a[4];
#pragma unroll
        for (int nf = 0; nf < 4; nf++) {
            const int c = n0 + wn * 32 + nf * 8 + (L & 3) * 2;
            t0a[nf] = __ldg((const float2*)(g_t1 + (size_t)bb0 * H_DIM + c));
            t1a[nf] = __ldg((const float2*)(g_t1 + (size_t)bb1 * H_DIM + c));
        }
        float rp0 = 0.f, rp1 = 0.f;
#pragma unroll
        for (int nf = 0; nf < 4; nf++) {
            const int cl = wn * 32 + nf * 8 + (L & 3) * 2;
            float x[4], y[4];
#pragma unroll
            for (int e = 0; e < 4; e++) {
                x[e] = fmaf(W11, (float)s11[mf][nf][e],
                       fmaf(WMID, (float)smid[mf][nf][e],
                            W00 * (float)s00[mf][nf][e]));
            }
            x[0] += t0a[nf].x; x[1] += t0a[nf].y;
            x[2] += t1a[nf].x; x[3] += t1a[nf].y;
            tanh4(x, y);
            rp0 += y[0] * vs[cl] + y[1] * vs[cl + 1];
            rp1 += y[2] * vs[cl] + y[3] * vs[cl + 1];
        }
        rp0 += __shfl_xor_sync(0xffffffffu, rp0, 1);
        rp0 += __shfl_xor_sync(0xffffffffu, rp0, 2);
        rp1 += __shfl_xor_sync(0xffffffffu, rp1, 1);
        rp1 += __shfl_xor_sync(0xffffffffu, rp1, 2);
        if ((L & 3) == 0) {
            atomicAdd(&srow[wm * 64 + mf * 16 + q], rp0);
            atomicAdd(&srow[wm * 64 + mf * 16 + q + 8], rp1);
        }
    }
    __syncthreads();
    {
        int rowg = m0 + tid;
        atomicAdd(&g_scores[(rowg & 31) * S_LEN + (rowg >> 5)], srow[tid]);
    }
}

// ---------------- softmax ----------------
__global__ void k2_softmax(const int* __restrict__ lens, float* __restrict__ wout) {
    __shared__ float red[256];
    int b = blockIdx.x;
    int len = lens[b];
    const float* sc = g_scores + (size_t)b * S_LEN;
    int tid = threadIdx.x;

    float mx = -3.4e38f;
    for (int s = tid; s < len; s += 256) mx = fmaxf(mx, sc[s]);
    red[tid] = mx;
    __syncthreads();
    for (int off = 128; off; off >>= 1) {
        if (tid < off) red[tid] = fmaxf(red[tid], red[tid + off]);
        __syncthreads();
    }
    mx = red[0];
    __syncthreads();

    float sum = 0.f;
    for (int s = tid; s < len; s += 256) sum += expf(sc[s] - mx);
    red[tid] = sum;
    __syncthreads();
    for (int off = 128; off; off >>= 1) {
        if (tid < off) red[tid] += red[tid + off];
        __syncthreads();
    }
    float inv = 1.f / red[0];

    for (int s = tid; s < S_LEN; s += 256)
        wout[(size_t)b * S_LEN + s] = (s < len) ? expf(sc[s] - mx) * inv : 0.f;
}

// ---------------- context ----------------
#define NCHUNK 64
__global__ void k3_context(const float* __restrict__ enc,
                           const float* __restrict__ wts,
                           const int* __restrict__ lens,
                           float* __restrict__ ctx) {
    int b = blockIdx.y;
    int len = lens[b];
    int s0 = blockIdx.x * (S_LEN / NCHUNK);
    int s1 = min(s0 + (S_LEN / NCHUNK), len);
    if (s0 >= s1) return;
    int h = threadIdx.x * 4;
    float4 acc = make_float4(0.f, 0.f, 0.f, 0.f);
    for (int s = s0; s < s1; s++) {
        float w = __ldg(&wts[(size_t)b * S_LEN + s]);
        float4 e = *(const float4*)(enc + ((size_t)(s * B_DIM + b)) * H_DIM + h);
        acc.x += w * e.x; acc.y += w * e.y; acc.z += w * e.z; acc.w += w * e.w;
    }
    float* c = ctx + (size_t)b * H_DIM + h;
    atomicAdd(c + 0, acc.x);
    atomicAdd(c + 1, acc.y);
    atomicAdd(c + 2, acc.z);
    atomicAdd(c + 3, acc.w);
}

// ---------------- launcher ----------------
extern "C" void kernel_launch(void* const* d_in, const int* in_sizes, int n_in,
                              void* d_out, int out_size) {
    const float* hidden = (const float*)d_in[0];
    const float* enc    = (const float*)d_in[1];
    const int*   lens   = (const int*)d_in[2];
    const float* attn_w = (const float*)d_in[3];
    const float* attn_b = (const float*)d_in[4];
    const float* v      = (const float*)d_in[5];

    float* out = (float*)d_out;
    float* ctx = out;
    float* wts = out + B_DIM * H_DIM;

    cudaFuncSetAttribute(k1_gemm, cudaFuncAttributeMaxDynamicSharedMemorySize, K1_SMEM);

    k_prep<<<PREP_GRID, 256>>>((const float4*)enc, attn_w, attn_b, hidden, ctx);
    dim3 g1(H_DIM / BN, M_TOT / BM);     // (16, 512), n fastest -> A reuse in L2
    k1_gemm<<<g1, 128, K1_SMEM>>>(v);
    k2_softmax<<<B_DIM, 256>>>(lens, wts);
    dim3 g3(NCHUNK, B_DIM);
    k3_context<<<g3, 256>>>(enc, wts, lens, ctx);
}

// round 12
// speedup vs baseline: 3.8551x; 3.8551x over previous
#include <cuda_runtime.h>
#include <cuda_bf16.h>

#define S_LEN 2048
#define B_DIM 32
#define H_DIM 1024
#define M_TOT (S_LEN * B_DIM)

// ---------------- scratch ----------------
__device__ __nv_bfloat16 g_enc_hi[(size_t)M_TOT * H_DIM];   // 128 MB
__device__ __nv_bfloat16 g_enc_lo[(size_t)M_TOT * H_DIM];   // 128 MB
__device__ __nv_bfloat16 g_w2_hi[H_DIM * H_DIM];
__device__ __nv_bfloat16 g_w2_lo[H_DIM * H_DIM];
__device__ float g_t1[B_DIM * H_DIM];
__device__ float g_scores[B_DIM * S_LEN];

// ---------------- helpers ----------------
__device__ __forceinline__ unsigned smem_u32(const void* p) {
    unsigned a;
    asm("{ .reg .u64 t; cvta.to.shared.u64 t, %1; cvt.u32.u64 %0, t; }" : "=r"(a) : "l"(p));
    return a;
}
__device__ __forceinline__ uint4 ldsm_x4(unsigned addr) {
    uint4 r;
    asm volatile("ldmatrix.sync.aligned.m8n8.x4.shared.b16 {%0,%1,%2,%3}, [%4];"
                 : "=r"(r.x), "=r"(r.y), "=r"(r.z), "=r"(r.w) : "r"(addr));
    return r;
}
__device__ __forceinline__ void mma_bf16(float* c, uint4 a, unsigned b0, unsigned b1) {
    asm volatile(
        "mma.sync.aligned.m16n8k16.row.col.f32.bf16.bf16.f32 "
        "{%0,%1,%2,%3}, {%4,%5,%6,%7}, {%8,%9}, {%0,%1,%2,%3};"
        : "+f"(c[0]), "+f"(c[1]), "+f"(c[2]), "+f"(c[3])
        : "r"(a.x), "r"(a.y), "r"(a.z), "r"(a.w), "r"(b0), "r"(b1));
}
__device__ __forceinline__ unsigned pack_bf16x2(float f0, float f1) {
    unsigned r;
    asm("cvt.rn.bf16x2.f32 %0, %1, %2;" : "=r"(r) : "f"(f1), "f"(f0));
    return r;
}
__device__ __forceinline__ void cp_async16(unsigned sdst, const void* gsrc) {
    unsigned long long g;
    asm("cvta.to.global.u64 %0, %1;" : "=l"(g) : "l"(gsrc));
    asm volatile("cp.async.cg.shared.global [%0], [%1], 16;" :: "r"(sdst), "l"(g) : "memory");
}
#define CP_COMMIT() asm volatile("cp.async.commit_group;" ::: "memory")
#define CP_WAIT0()  asm volatile("cp.async.wait_group 0;" ::: "memory")
#define CP_WAIT1()  asm volatile("cp.async.wait_group 1;" ::: "memory")

// rational tanh, 4 at a time, one Newton-refined RCP
__device__ __forceinline__ void tanh4(const float* x, float* y) {
    float al[4], be[4];
#pragma unroll
    for (int i = 0; i < 4; i++) {
        float xc = fminf(fmaxf(x[i], -7.90531110763549805f), 7.90531110763549805f);
        float t = xc * xc;
        float a = -2.76076847742355e-16f;
        a = fmaf(a, t, 2.00018790482477e-13f);
        a = fmaf(a, t, -8.60467152213735e-11f);
        a = fmaf(a, t, 5.12229709037114e-08f);
        a = fmaf(a, t, 1.48572235717979e-05f);
        a = fmaf(a, t, 6.37261928875436e-04f);
        a = fmaf(a, t, 4.89352455891786e-03f);
        al[i] = xc * a;
        float b = 1.19825839466702e-06f;
        b = fmaf(b, t, 1.18534705686654e-04f);
        b = fmaf(b, t, 2.26843463243900e-03f);
        be[i] = fmaf(b, t, 4.89352518554385e-03f);
    }
    float p01 = be[0] * be[1];
    float p23 = be[2] * be[3];
    float p = p01 * p23;
    float r;
    asm("rcp.approx.f32 %0, %1;" : "=f"(r) : "f"(p));
    r = r * fmaf(-p, r, 2.0f);
    float q01 = r * p23, q23 = r * p01;
    y[0] = al[0] * (q01 * be[1]);
    y[1] = al[1] * (q01 * be[0]);
    y[2] = al[2] * (q23 * be[3]);
    y[3] = al[3] * (q23 * be[2]);
}

// ---------------- fused prep kernel ----------------
// enc: each thread handles 8 consecutive float4s (MLP=8, STG.128 stores)
#define PREP_ENC_BLKS   8192
#define PREP_W2_BLKS    1024
#define PREP_T1_BLKS    4096
#define PREP_INIT_BLKS  256
#define PREP_GRID (PREP_ENC_BLKS + PREP_W2_BLKS + PREP_T1_BLKS + PREP_INIT_BLKS)

__global__ void k_prep(const float4* __restrict__ enc4,
                       const float* __restrict__ attn_w,
                       const float* __restrict__ attn_b,
                       const float* __restrict__ hidden,
                       float* __restrict__ ctx) {
    int blk = blockIdx.x;
    int tid = threadIdx.x;
    if (blk < PREP_ENC_BLKS) {
        // 32 floats per thread: 8 x LDG.128 batched, 4+4 x STG.128
        size_t i0 = ((size_t)blk * 256 + tid) * 8;     // float4 index
        float4 x[8];
#pragma unroll
        for (int i = 0; i < 8; i++) x[i] = enc4[i0 + i];
        unsigned hi[16], lo[16];
#pragma unroll
        for (int i = 0; i < 8; i++) {
            float hx = __bfloat162float(__float2bfloat16(x[i].x));
            float hy = __bfloat162float(__float2bfloat16(x[i].y));
            float hz = __bfloat162float(__float2bfloat16(x[i].z));
            float hw = __bfloat162float(__float2bfloat16(x[i].w));
            hi[i * 2]     = pack_bf16x2(x[i].x, x[i].y);
            hi[i * 2 + 1] = pack_bf16x2(x[i].z, x[i].w);
            lo[i * 2]     = pack_bf16x2(x[i].x - hx, x[i].y - hy);
            lo[i * 2 + 1] = pack_bf16x2(x[i].z - hz, x[i].w - hw);
        }
        uint4* dh = (uint4*)(g_enc_hi + i0 * 4);       // i0*4 bf16 elements
        uint4* dl = (uint4*)(g_enc_lo + i0 * 4);
#pragma unroll
        for (int i = 0; i < 4; i++) {
            dh[i] = make_uint4(hi[i * 4], hi[i * 4 + 1], hi[i * 4 + 2], hi[i * 4 + 3]);
            dl[i] = make_uint4(lo[i * 4], lo[i * 4 + 1], lo[i * 4 + 2], lo[i * 4 + 3]);
        }
    } else if (blk < PREP_ENC_BLKS + PREP_W2_BLKS) {
        int i = (blk - PREP_ENC_BLKS) * 256 + tid;
        int row = i >> 8, c4 = i & 255;
        float4 x = *(const float4*)(attn_w + (size_t)row * (2 * H_DIM) + H_DIM + c4 * 4);
        float hx = __bfloat162float(__float2bfloat16(x.x));
        float hy = __bfloat162float(__float2bfloat16(x.y));
        float hz = __bfloat162float(__float2bfloat16(x.z));
        float hw = __bfloat162float(__float2bfloat16(x.w));
        ((uint2*)g_w2_hi)[i] = make_uint2(pack_bf16x2(x.x, x.y), pack_bf16x2(x.z, x.w));
        ((uint2*)g_w2_lo)[i] = make_uint2(pack_bf16x2(x.x - hx, x.y - hy),
                                          pack_bf16x2(x.z - hz, x.w - hw));
    } else if (blk < PREP_ENC_BLKS + PREP_W2_BLKS + PREP_T1_BLKS) {
        int w = (blk - PREP_ENC_BLKS - PREP_W2_BLKS) * 8 + (tid >> 5);
        int lane = tid & 31;
        int b = w >> 10;
        int h = w & (H_DIM - 1);
        const float4* hp = (const float4*)(hidden + (size_t)b * H_DIM);
        const float4* wp = (const float4*)(attn_w + (size_t)h * 2 * H_DIM);
        float acc = 0.f;
#pragma unroll
        for (int i = 0; i < 8; i++) {
            int idx = i * 32 + lane;
            float4 hv = hp[idx];
            float4 wv = wp[idx];
            acc += hv.x * wv.x + hv.y * wv.y + hv.z * wv.z + hv.w * wv.w;
        }
#pragma unroll
        for (int off = 16; off; off >>= 1) acc += __shfl_down_sync(0xffffffffu, acc, off);
        if (lane == 0) g_t1[w] = acc + attn_b[h];
    } else {
        int i = (blk - PREP_ENC_BLKS - PREP_W2_BLKS - PREP_T1_BLKS) * 256 + tid;
        if (i < B_DIM * S_LEN) g_scores[i] = 0.f;
        if (i < B_DIM * H_DIM) ctx[i] = 0.f;
    }
}

// ---------------- K1: 128x128 CTA (4 warps), 2 CTAs/SM, 3-stage cp.async ----------------
#define BM 128
#define BN 128
#define BK 32
#define A_HI 0
#define A_LO 8192
#define B_HI 16384
#define B_LO 24576
#define STAGE_B 32768
#define NSTAGE 3
#define VS_OFF  (NSTAGE * STAGE_B)          // 98304: 128 f32
#define SROW_OFF (VS_OFF + 512)             // 98816: 128 f32
#define K1_SMEM  (SROW_OFF + 512)           // 99328

__device__ __forceinline__ unsigned sw_off(int row, int c16) {
    return (unsigned)row * 64u + (unsigned)((c16 ^ ((row >> 1) & 3)) << 4);
}

__device__ __forceinline__ void fill_stage(unsigned sb, int m0, int n0, int kk, int tid) {
#pragma unroll
    for (int i = 0; i < 4; i++) {
        int idx = i * 128 + tid;
        int row = idx >> 2, c16 = idx & 3;
        size_t goff = (size_t)(m0 + row) * H_DIM + kk + c16 * 8;
        unsigned soff = sw_off(row, c16);
        cp_async16(sb + A_HI + soff, g_enc_hi + goff);
        cp_async16(sb + A_LO + soff, g_enc_lo + goff);
    }
#pragma unroll
    for (int i = 0; i < 4; i++) {
        int idx = i * 128 + tid;
        int row = idx >> 2, c16 = idx & 3;
        size_t goff = (size_t)(n0 + row) * H_DIM + kk + c16 * 8;
        unsigned soff = sw_off(row, c16);
        cp_async16(sb + B_HI + soff, g_w2_hi + goff);
        cp_async16(sb + B_LO + soff, g_w2_lo + goff);
    }
}

__global__ void __launch_bounds__(128, 2) k1_gemm(const float* __restrict__ v) {
    extern __shared__ char smem[];
    const unsigned sbase = smem_u32(smem);
    const int tid = threadIdx.x;
    const int wid = tid >> 5;
    const int L = tid & 31;
    const int wm = wid & 1;
    const int wn = wid >> 1;
    const int m0 = blockIdx.y * BM;
    const int n0 = blockIdx.x * BN;

    float* vs = (float*)(smem + VS_OFF);
    float* srow = (float*)(smem + SROW_OFF);
    vs[tid] = v[n0 + tid];
    srow[tid] = 0.f;

    fill_stage(sbase, m0, n0, 0, tid);
    CP_COMMIT();
    fill_stage(sbase + STAGE_B, m0, n0, BK, tid);
    CP_COMMIT();

    float acc[4][8][4];
#pragma unroll
    for (int i = 0; i < 4; i++)
#pragma unroll
        for (int j = 0; j < 8; j++)
#pragma unroll
            for (int e = 0; e < 4; e++) acc[i][j][e] = 0.f;

    const int a_r = wm * 64 + ((L >> 3) & 1) * 8 + (L & 7);
    const int a_c = (L >> 4);
    const int b_r = wn * 64 + (L >> 4) * 8 + (L & 7);
    const int b_c = ((L >> 3) & 1);

    const int NKT = H_DIM / BK;              // 32
    int slot = 0, nslot = 2;
    for (int kt = 0; kt < NKT; kt++) {
        if (kt + 1 < NKT) { CP_WAIT1(); } else { CP_WAIT0(); }
        __syncthreads();
        if (kt + 2 < NKT) {
            fill_stage(sbase + nslot * STAGE_B, m0, n0, (kt + 2) * BK, tid);
            CP_COMMIT();
        }
        const unsigned sb = sbase + slot * STAGE_B;
#pragma unroll
        for (int ks = 0; ks < 2; ks++) {
            uint4 ah[4], al[4], bh[4], bl[4];
#pragma unroll
            for (int mf = 0; mf < 4; mf++) {
                int row = a_r + mf * 16;
                unsigned off = sw_off(row, ks * 2 + a_c);
                ah[mf] = ldsm_x4(sb + A_HI + off);
                al[mf] = ldsm_x4(sb + A_LO + off);
            }
#pragma unroll
            for (int nf2 = 0; nf2 < 4; nf2++) {
                int row = b_r + nf2 * 16;
                unsigned off = sw_off(row, ks * 2 + b_c);
                bh[nf2] = ldsm_x4(sb + B_HI + off);
                bl[nf2] = ldsm_x4(sb + B_LO + off);
            }
#pragma unroll
            for (int mf = 0; mf < 4; mf++)
#pragma unroll
                for (int nf2 = 0; nf2 < 4; nf2++) {
                    mma_bf16(acc[mf][nf2 * 2],     ah[mf], bh[nf2].x, bh[nf2].y);
                    mma_bf16(acc[mf][nf2 * 2 + 1], ah[mf], bh[nf2].z, bh[nf2].w);
                }
#pragma unroll
            for (int mf = 0; mf < 4; mf++)
#pragma unroll
                for (int nf2 = 0; nf2 < 4; nf2++) {
                    mma_bf16(acc[mf][nf2 * 2],     ah[mf], bl[nf2].x, bl[nf2].y);
                    mma_bf16(acc[mf][nf2 * 2 + 1], ah[mf], bl[nf2].z, bl[nf2].w);
                }
#pragma unroll
            for (int mf = 0; mf < 4; mf++)
#pragma unroll
                for (int nf2 = 0; nf2 < 4; nf2++) {
                    mma_bf16(acc[mf][nf2 * 2],     al[mf], bh[nf2].x, bh[nf2].y);
                    mma_bf16(acc[mf][nf2 * 2 + 1], al[mf], bh[nf2].z, bh[nf2].w);
                }
        }
        slot = (slot == 2) ? 0 : slot + 1;
        nslot = (nslot == 2) ? 0 : nslot + 1;
    }

    // ---------------- epilogue: batched t1 loads + tanh + v-dot + row reduce ----------------
    const int q = L >> 2;
#pragma unroll
    for (int mf = 0; mf < 4; mf++) {
        const int r0 = m0 + wm * 64 + mf * 16 + q;
        const int bb0 = r0 & 31;
        const int bb1 = (r0 + 8) & 31;
        float2 t0a[8], t1a[8];
#pragma unroll
        for (int nf = 0; nf < 8; nf++) {
            const int c = n0 + wn * 64 + nf * 8 + (L & 3) * 2;
            t0a[nf] = __ldg((const float2*)(g_t1 + (size_t)bb0 * H_DIM + c));
            t1a[nf] = __ldg((const float2*)(g_t1 + (size_t)bb1 * H_DIM + c));
        }
        float rp0 = 0.f, rp1 = 0.f;
#pragma unroll
        for (int nf = 0; nf < 8; nf++) {
            const int cl = wn * 64 + nf * 8 + (L & 3) * 2;
            float x[4], y[4];
            x[0] = acc[mf][nf][0] + t0a[nf].x;
            x[1] = acc[mf][nf][1] + t0a[nf].y;
            x[2] = acc[mf][nf][2] + t1a[nf].x;
            x[3] = acc[mf][nf][3] + t1a[nf].y;
            tanh4(x, y);
            rp0 += y[0] * vs[cl] + y[1] * vs[cl + 1];
            rp1 += y[2] * vs[cl] + y[3] * vs[cl + 1];
        }
        rp0 += __shfl_xor_sync(0xffffffffu, rp0, 1);
        rp0 += __shfl_xor_sync(0xffffffffu, rp0, 2);
        rp1 += __shfl_xor_sync(0xffffffffu, rp1, 1);
        rp1 += __shfl_xor_sync(0xffffffffu, rp1, 2);
        if ((L & 3) == 0) {
            atomicAdd(&srow[wm * 64 + mf * 16 + q], rp0);
            atomicAdd(&srow[wm * 64 + mf * 16 + q + 8], rp1);
        }
    }
    __syncthreads();
    {
        int rowg = m0 + tid;
        atomicAdd(&g_scores[(rowg & 31) * S_LEN + (rowg >> 5)], srow[tid]);
    }
}

// ---------------- softmax ----------------
__global__ void k2_softmax(const int* __restrict__ lens, float* __restrict__ wout) {
    __shared__ float red[256];
    int b = blockIdx.x;
    int len = lens[b];
    const float* sc = g_scores + (size_t)b * S_LEN;
    int tid = threadIdx.x;

    float mx = -3.4e38f;
    for (int s = tid; s < len; s += 256) mx = fmaxf(mx, sc[s]);
    red[tid] = mx;
    __syncthreads();
    for (int off = 128; off; off >>= 1) {
        if (tid < off) red[tid] = fmaxf(red[tid], red[tid + off]);
        __syncthreads();
    }
    mx = red[0];
    __syncthreads();

    float sum = 0.f;
    for (int s = tid; s < len; s += 256) sum += expf(sc[s] - mx);
    red[tid] = sum;
    __syncthreads();
    for (int off = 128; off; off >>= 1) {
        if (tid < off) red[tid] += red[tid + off];
        __syncthreads();
    }
    float inv = 1.f / red[0];

    for (int s = tid; s < S_LEN; s += 256)
        wout[(size_t)b * S_LEN + s] = (s < len) ? expf(sc[s] - mx) * inv : 0.f;
}

// ---------------- context ----------------
#define NCHUNK 64
__global__ void k3_context(const float* __restrict__ enc,
                           const float* __restrict__ wts,
                           const int* __restrict__ lens,
                           float* __restrict__ ctx) {
    int b = blockIdx.y;
    int len = lens[b];
    int s0 = blockIdx.x * (S_LEN / NCHUNK);
    int s1 = min(s0 + (S_LEN / NCHUNK), len);
    if (s0 >= s1) return;
    int h = threadIdx.x * 4;
    float4 acc = make_float4(0.f, 0.f, 0.f, 0.f);
    for (int s = s0; s < s1; s++) {
        float w = __ldg(&wts[(size_t)b * S_LEN + s]);
        float4 e = *(const float4*)(enc + ((size_t)(s * B_DIM + b)) * H_DIM + h);
        acc.x += w * e.x; acc.y += w * e.y; acc.z += w * e.z; acc.w += w * e.w;
    }
    float* c = ctx + (size_t)b * H_DIM + h;
    atomicAdd(c + 0, acc.x);
    atomicAdd(c + 1, acc.y);
    atomicAdd(c + 2, acc.z);
    atomicAdd(c + 3, acc.w);
}

// ---------------- launcher ----------------
extern "C" void kernel_launch(void* const* d_in, const int* in_sizes, int n_in,
                              void* d_out, int out_size) {
    const float* hidden = (const float*)d_in[0];
    const float* enc    = (const float*)d_in[1];
    const int*   lens   = (const int*)d_in[2];
    const float* attn_w = (const float*)d_in[3];
    const float* attn_b = (const float*)d_in[4];
    const float* v      = (const float*)d_in[5];

    float* out = (float*)d_out;
    float* ctx = out;
    float* wts = out + B_DIM * H_DIM;

    cudaFuncSetAttribute(k1_gemm, cudaFuncAttributeMaxDynamicSharedMemorySize, K1_SMEM);

    k_prep<<<PREP_GRID, 256>>>((const float4*)enc, attn_w, attn_b, hidden, ctx);
    dim3 g1(H_DIM / BN, M_TOT / BM);     // (8, 512), n fastest -> A reuse in L2
    k1_gemm<<<g1, 128, K1_SMEM>>>(v);
    k2_softmax<<<B_DIM, 256>>>(lens, wts);
    dim3 g3(NCHUNK, B_DIM);
    k3_context<<<g3, 256>>>(enc, wts, lens, ctx);
}

// round 13
// speedup vs baseline: 7.3705x; 1.9119x over previous
#include <cuda_runtime.h>
#include <cuda_bf16.h>

#define S_LEN 2048
#define B_DIM 32
#define H_DIM 1024
#define M_TOT (S_LEN * B_DIM)

// ---------------- scratch ----------------
__device__ __nv_bfloat16 g_enc_hi[(size_t)M_TOT * H_DIM];   // 128 MB
__device__ __nv_bfloat16 g_enc_lo[(size_t)M_TOT * H_DIM];   // 128 MB
__device__ __nv_bfloat16 g_w2_hi[H_DIM * H_DIM];
__device__ __nv_bfloat16 g_w2_lo[H_DIM * H_DIM];
__device__ float g_t1[B_DIM * H_DIM];
__device__ float g_scores[B_DIM * S_LEN];
__device__ int g_off[B_DIM + 1];
__device__ int g_total;

// ---------------- helpers ----------------
__device__ __forceinline__ unsigned smem_u32(const void* p) {
    unsigned a;
    asm("{ .reg .u64 t; cvta.to.shared.u64 t, %1; cvt.u32.u64 %0, t; }" : "=r"(a) : "l"(p));
    return a;
}
__device__ __forceinline__ uint4 ldsm_x4(unsigned addr) {
    uint4 r;
    asm volatile("ldmatrix.sync.aligned.m8n8.x4.shared.b16 {%0,%1,%2,%3}, [%4];"
                 : "=r"(r.x), "=r"(r.y), "=r"(r.z), "=r"(r.w) : "r"(addr));
    return r;
}
__device__ __forceinline__ void mma_bf16(float* c, uint4 a, unsigned b0, unsigned b1) {
    asm volatile(
        "mma.sync.aligned.m16n8k16.row.col.f32.bf16.bf16.f32 "
        "{%0,%1,%2,%3}, {%4,%5,%6,%7}, {%8,%9}, {%0,%1,%2,%3};"
        : "+f"(c[0]), "+f"(c[1]), "+f"(c[2]), "+f"(c[3])
        : "r"(a.x), "r"(a.y), "r"(a.z), "r"(a.w), "r"(b0), "r"(b1));
}
__device__ __forceinline__ unsigned pack_bf16x2(float f0, float f1) {
    unsigned r;
    asm("cvt.rn.bf16x2.f32 %0, %1, %2;" : "=r"(r) : "f"(f1), "f"(f0));
    return r;
}
__device__ __forceinline__ void cp_async16(unsigned sdst, const void* gsrc) {
    unsigned long long g;
    asm("cvta.to.global.u64 %0, %1;" : "=l"(g) : "l"(gsrc));
    asm volatile("cp.async.cg.shared.global [%0], [%1], 16;" :: "r"(sdst), "l"(g) : "memory");
}
#define CP_COMMIT() asm volatile("cp.async.commit_group;" ::: "memory")
#define CP_WAIT0()  asm volatile("cp.async.wait_group 0;" ::: "memory")
#define CP_WAIT1()  asm volatile("cp.async.wait_group 1;" ::: "memory")

// compact index -> (batch, s): largest b with soff[b] <= ci
__device__ __forceinline__ int2 rowmap(const int* soff, int ci) {
    int lo = 0, hi = 32;
    while (lo < hi) {
        int mid = (lo + hi + 1) >> 1;
        if (soff[mid] <= ci) lo = mid; else hi = mid - 1;
    }
    return make_int2(lo, ci - soff[lo]);
}

// rational tanh, 4 at a time, one Newton-refined RCP
__device__ __forceinline__ void tanh4(const float* x, float* y) {
    float al[4], be[4];
#pragma unroll
    for (int i = 0; i < 4; i++) {
        float xc = fminf(fmaxf(x[i], -7.90531110763549805f), 7.90531110763549805f);
        float t = xc * xc;
        float a = -2.76076847742355e-16f;
        a = fmaf(a, t, 2.00018790482477e-13f);
        a = fmaf(a, t, -8.60467152213735e-11f);
        a = fmaf(a, t, 5.12229709037114e-08f);
        a = fmaf(a, t, 1.48572235717979e-05f);
        a = fmaf(a, t, 6.37261928875436e-04f);
        a = fmaf(a, t, 4.89352455891786e-03f);
        al[i] = xc * a;
        float b = 1.19825839466702e-06f;
        b = fmaf(b, t, 1.18534705686654e-04f);
        b = fmaf(b, t, 2.26843463243900e-03f);
        be[i] = fmaf(b, t, 4.89352518554385e-03f);
    }
    float p01 = be[0] * be[1];
    float p23 = be[2] * be[3];
    float p = p01 * p23;
    float r;
    asm("rcp.approx.f32 %0, %1;" : "=f"(r) : "f"(p));
    r = r * fmaf(-p, r, 2.0f);
    float q01 = r * p23, q23 = r * p01;
    y[0] = al[0] * (q01 * be[1]);
    y[1] = al[1] * (q01 * be[0]);
    y[2] = al[2] * (q23 * be[3]);
    y[3] = al[3] * (q23 * be[2]);
}

// ---------------- fused prep kernel (R10 enc batching + len skip + prefix) ----------------
#define PREP_ENC_BLKS   16384
#define PREP_W2_BLKS    1024
#define PREP_T1_BLKS    4096
#define PREP_INIT_BLKS  256
#define PREP_GRID (PREP_ENC_BLKS + PREP_W2_BLKS + PREP_T1_BLKS + PREP_INIT_BLKS + 1)

__global__ void k_prep(const float4* __restrict__ enc4,
                       const float* __restrict__ attn_w,
                       const float* __restrict__ attn_b,
                       const float* __restrict__ hidden,
                       const int* __restrict__ lens,
                       float* __restrict__ ctx) {
    int blk = blockIdx.x;
    int tid = threadIdx.x;
    if (blk < PREP_ENC_BLKS) {
        size_t i0 = ((size_t)blk * 256 + tid) * 4;     // float4 index; 256 float4/row
        int row = (int)(i0 >> 8);
        int b = row & (B_DIM - 1), s = row >> 5;
        if (s >= __ldg(&lens[b])) return;              // inactive row: never read by GEMM
        float4 x[4];
#pragma unroll
        for (int i = 0; i < 4; i++) x[i] = enc4[i0 + i];
        unsigned hi[8], lo[8];
#pragma unroll
        for (int i = 0; i < 4; i++) {
            float hx = __bfloat162float(__float2bfloat16(x[i].x));
            float hy = __bfloat162float(__float2bfloat16(x[i].y));
            float hz = __bfloat162float(__float2bfloat16(x[i].z));
            float hw = __bfloat162float(__float2bfloat16(x[i].w));
            hi[i * 2]     = pack_bf16x2(x[i].x, x[i].y);
            hi[i * 2 + 1] = pack_bf16x2(x[i].z, x[i].w);
            lo[i * 2]     = pack_bf16x2(x[i].x - hx, x[i].y - hy);
            lo[i * 2 + 1] = pack_bf16x2(x[i].z - hz, x[i].w - hw);
        }
        uint4* dh = (uint4*)(g_enc_hi + i0 * 4);
        uint4* dl = (uint4*)(g_enc_lo + i0 * 4);
        dh[0] = make_uint4(hi[0], hi[1], hi[2], hi[3]);
        dh[1] = make_uint4(hi[4], hi[5], hi[6], hi[7]);
        dl[0] = make_uint4(lo[0], lo[1], lo[2], lo[3]);
        dl[1] = make_uint4(lo[4], lo[5], lo[6], lo[7]);
    } else if (blk < PREP_ENC_BLKS + PREP_W2_BLKS) {
        int i = (blk - PREP_ENC_BLKS) * 256 + tid;
        int row = i >> 8, c4 = i & 255;
        float4 x = *(const float4*)(attn_w + (size_t)row * (2 * H_DIM) + H_DIM + c4 * 4);
        float hx = __bfloat162float(__float2bfloat16(x.x));
        float hy = __bfloat162float(__float2bfloat16(x.y));
        float hz = __bfloat162float(__float2bfloat16(x.z));
        float hw = __bfloat162float(__float2bfloat16(x.w));
        ((uint2*)g_w2_hi)[i] = make_uint2(pack_bf16x2(x.x, x.y), pack_bf16x2(x.z, x.w));
        ((uint2*)g_w2_lo)[i] = make_uint2(pack_bf16x2(x.x - hx, x.y - hy),
                                          pack_bf16x2(x.z - hz, x.w - hw));
    } else if (blk < PREP_ENC_BLKS + PREP_W2_BLKS + PREP_T1_BLKS) {
        int w = (blk - PREP_ENC_BLKS - PREP_W2_BLKS) * 8 + (tid >> 5);
        int lane = tid & 31;
        int b = w >> 10;
        int h = w & (H_DIM - 1);
        const float4* hp = (const float4*)(hidden + (size_t)b * H_DIM);
        const float4* wp = (const float4*)(attn_w + (size_t)h * 2 * H_DIM);
        float acc = 0.f;
#pragma unroll
        for (int i = 0; i < 8; i++) {
            int idx = i * 32 + lane;
            float4 hv = hp[idx];
            float4 wv = wp[idx];
            acc += hv.x * wv.x + hv.y * wv.y + hv.z * wv.z + hv.w * wv.w;
        }
#pragma unroll
        for (int off = 16; off; off >>= 1) acc += __shfl_down_sync(0xffffffffu, acc, off);
        if (lane == 0) g_t1[w] = acc + attn_b[h];
    } else if (blk < PREP_ENC_BLKS + PREP_W2_BLKS + PREP_T1_BLKS + PREP_INIT_BLKS) {
        int i = (blk - PREP_ENC_BLKS - PREP_W2_BLKS - PREP_T1_BLKS) * 256 + tid;
        if (i < B_DIM * S_LEN) g_scores[i] = 0.f;
        if (i < B_DIM * H_DIM) ctx[i] = 0.f;
    } else {
        if (tid == 0) {
            int acc = 0;
            g_off[0] = 0;
            for (int b = 0; b < B_DIM; b++) { acc += lens[b]; g_off[b + 1] = acc; }
            g_total = acc;
        }
    }
}

// ---------------- K1: compacted-row GEMM, 128x128 CTA, 2 CTAs/SM ----------------
#define BM 128
#define BN 128
#define BK 32
#define A_HI 0
#define A_LO 8192
#define B_HI 16384
#define B_LO 24576
#define STAGE_B 32768
#define NSTAGE 3
#define VS_OFF  (NSTAGE * STAGE_B)          // 98304: 128 f32
#define SROW_OFF (VS_OFF + 512)             // 98816: 128 f32
#define SOFF_OFF (SROW_OFF + 512)           // 99328: 33 ints
#define K1_SMEM  (SOFF_OFF + 144)           // 99472

__device__ __forceinline__ unsigned sw_off(int row, int c16) {
    return (unsigned)row * 64u + (unsigned)((c16 ^ ((row >> 1) & 3)) << 4);
}

// A rows precomputed (compact->global), B dense
__device__ __forceinline__ void fill_stage(unsigned sb, const size_t* gA, int n0,
                                           int kk, int tid) {
    const int c16 = tid & 3;
    const int lr = tid >> 2;
#pragma unroll
    for (int i = 0; i < 4; i++) {
        size_t goff = gA[i] + kk + c16 * 8;
        unsigned soff = sw_off(i * 32 + lr, c16);
        cp_async16(sb + A_HI + soff, g_enc_hi + goff);
        cp_async16(sb + A_LO + soff, g_enc_lo + goff);
    }
#pragma unroll
    for (int i = 0; i < 4; i++) {
        int idx = i * 128 + tid;
        int row = idx >> 2;
        size_t goff = (size_t)(n0 + row) * H_DIM + kk + c16 * 8;
        unsigned soff = sw_off(row, c16);
        cp_async16(sb + B_HI + soff, g_w2_hi + goff);
        cp_async16(sb + B_LO + soff, g_w2_lo + goff);
    }
}

__global__ void __launch_bounds__(128, 2) k1_gemm(const float* __restrict__ v) {
    const int total = g_total;
    const int m0c = blockIdx.y * BM;
    if (m0c >= total) return;

    extern __shared__ char smem[];
    const unsigned sbase = smem_u32(smem);
    const int tid = threadIdx.x;
    const int wid = tid >> 5;
    const int L = tid & 31;
    const int wm = wid & 1;
    const int wn = wid >> 1;
    const int n0 = blockIdx.x * BN;

    float* vs = (float*)(smem + VS_OFF);
    float* srow = (float*)(smem + SROW_OFF);
    int* soff = (int*)(smem + SOFF_OFF);
    vs[tid] = v[n0 + tid];
    srow[tid] = 0.f;
    if (tid < 33) soff[tid] = g_off[tid];
    __syncthreads();

    // precompute the 4 A-row global bases for this thread (fixed across ktiles)
    size_t gA[4];
#pragma unroll
    for (int i = 0; i < 4; i++) {
        int ci = m0c + i * 32 + (tid >> 2);
        ci = min(ci, total - 1);
        int2 bs = rowmap(soff, ci);
        gA[i] = (size_t)(bs.y * B_DIM + bs.x) * H_DIM;   // r = s*B + b
    }

    fill_stage(sbase, gA, n0, 0, tid);
    CP_COMMIT();
    fill_stage(sbase + STAGE_B, gA, n0, BK, tid);
    CP_COMMIT();

    float acc[4][8][4];
#pragma unroll
    for (int i = 0; i < 4; i++)
#pragma unroll
        for (int j = 0; j < 8; j++)
#pragma unroll
            for (int e = 0; e < 4; e++) acc[i][j][e] = 0.f;

    const int a_r = wm * 64 + ((L >> 3) & 1) * 8 + (L & 7);
    const int a_c = (L >> 4);
    const int b_r = wn * 64 + (L >> 4) * 8 + (L & 7);
    const int b_c = ((L >> 3) & 1);

    const int NKT = H_DIM / BK;              // 32
    int slot = 0, nslot = 2;
    for (int kt = 0; kt < NKT; kt++) {
        if (kt + 1 < NKT) { CP_WAIT1(); } else { CP_WAIT0(); }
        __syncthreads();
        if (kt + 2 < NKT) {
            fill_stage(sbase + nslot * STAGE_B, gA, n0, (kt + 2) * BK, tid);
            CP_COMMIT();
        }
        const unsigned sb = sbase + slot * STAGE_B;
#pragma unroll
        for (int ks = 0; ks < 2; ks++) {
            uint4 ah[4], al[4], bh[4], bl[4];
#pragma unroll
            for (int mf = 0; mf < 4; mf++) {
                int row = a_r + mf * 16;
                unsigned off = sw_off(row, ks * 2 + a_c);
                ah[mf] = ldsm_x4(sb + A_HI + off);
                al[mf] = ldsm_x4(sb + A_LO + off);
            }
#pragma unroll
            for (int nf2 = 0; nf2 < 4; nf2++) {
                int row = b_r + nf2 * 16;
                unsigned off = sw_off(row, ks * 2 + b_c);
                bh[nf2] = ldsm_x4(sb + B_HI + off);
                bl[nf2] = ldsm_x4(sb + B_LO + off);
            }
#pragma unroll
            for (int mf = 0; mf < 4; mf++)
#pragma unroll
                for (int nf2 = 0; nf2 < 4; nf2++) {
                    mma_bf16(acc[mf][nf2 * 2],     ah[mf], bh[nf2].x, bh[nf2].y);
                    mma_bf16(acc[mf][nf2 * 2 + 1], ah[mf], bh[nf2].z, bh[nf2].w);
                }
#pragma unroll
            for (int mf = 0; mf < 4; mf++)
#pragma unroll
                for (int nf2 = 0; nf2 < 4; nf2++) {
                    mma_bf16(acc[mf][nf2 * 2],     ah[mf], bl[nf2].x, bl[nf2].y);
                    mma_bf16(acc[mf][nf2 * 2 + 1], ah[mf], bl[nf2].z, bl[nf2].w);
                }
#pragma unroll
            for (int mf = 0; mf < 4; mf++)
#pragma unroll
                for (int nf2 = 0; nf2 < 4; nf2++) {
                    mma_bf16(acc[mf][nf2 * 2],     al[mf], bh[nf2].x, bh[nf2].y);
                    mma_bf16(acc[mf][nf2 * 2 + 1], al[mf], bh[nf2].z, bh[nf2].w);
                }
        }
        slot = (slot == 2) ? 0 : slot + 1;
        nslot = (nslot == 2) ? 0 : nslot + 1;
    }

    // ---------------- epilogue ----------------
    const int q = L >> 2;
#pragma unroll
    for (int mf = 0; mf < 4; mf++) {
        const int rc0 = m0c + wm * 64 + mf * 16 + q;
        const int rc1 = rc0 + 8;
        int2 bs0 = rowmap(soff, min(rc0, total - 1));
        int2 bs1 = rowmap(soff, min(rc1, total - 1));
        float2 t0a[8], t1a[8];
#pragma unroll
        for (int nf = 0; nf < 8; nf++) {
            const int c = n0 + wn * 64 + nf * 8 + (L & 3) * 2;
            t0a[nf] = __ldg((const float2*)(g_t1 + (size_t)bs0.x * H_DIM + c));
            t1a[nf] = __ldg((const float2*)(g_t1 + (size_t)bs1.x * H_DIM + c));
        }
        float rp0 = 0.f, rp1 = 0.f;
#pragma unroll
        for (int nf = 0; nf < 8; nf++) {
            const int cl = wn * 64 + nf * 8 + (L & 3) * 2;
            float x[4], y[4];
            x[0] = acc[mf][nf][0] + t0a[nf].x;
            x[1] = acc[mf][nf][1] + t0a[nf].y;
            x[2] = acc[mf][nf][2] + t1a[nf].x;
            x[3] = acc[mf][nf][3] + t1a[nf].y;
            tanh4(x, y);
            rp0 += y[0] * vs[cl] + y[1] * vs[cl + 1];
            rp1 += y[2] * vs[cl] + y[3] * vs[cl + 1];
        }
        rp0 += __shfl_xor_sync(0xffffffffu, rp0, 1);
        rp0 += __shfl_xor_sync(0xffffffffu, rp0, 2);
        rp1 += __shfl_xor_sync(0xffffffffu, rp1, 1);
        rp1 += __shfl_xor_sync(0xffffffffu, rp1, 2);
        if ((L & 3) == 0) {
            atomicAdd(&srow[wm * 64 + mf * 16 + q], rp0);
            atomicAdd(&srow[wm * 64 + mf * 16 + q + 8], rp1);
        }
    }
    __syncthreads();
    {
        int rc = m0c + tid;
        if (rc < total) {
            int2 bs = rowmap(soff, rc);
            atomicAdd(&g_scores[bs.x * S_LEN + bs.y], srow[tid]);
        }
    }
}

// ---------------- softmax ----------------
__global__ void k2_softmax(const int* __restrict__ lens, float* __restrict__ wout) {
    __shared__ float red[256];
    int b = blockIdx.x;
    int len = lens[b];
    const float* sc = g_scores + (size_t)b * S_LEN;
    int tid = threadIdx.x;

    float mx = -3.4e38f;
    for (int s = tid; s < len; s += 256) mx = fmaxf(mx, sc[s]);
    red[tid] = mx;
    __syncthreads();
    for (int off = 128; off; off >>= 1) {
        if (tid < off) red[tid] = fmaxf(red[tid], red[tid + off]);
        __syncthreads();
    }
    mx = red[0];
    __syncthreads();

    float sum = 0.f;
    for (int s = tid; s < len; s += 256) sum += expf(sc[s] - mx);
    red[tid] = sum;
    __syncthreads();
    for (int off = 128; off; off >>= 1) {
        if (tid < off) red[tid] += red[tid + off];
        __syncthreads();
    }
    float inv = 1.f / red[0];

    for (int s = tid; s < S_LEN; s += 256)
        wout[(size_t)b * S_LEN + s] = (s < len) ? expf(sc[s] - mx) * inv : 0.f;
}

// ---------------- context ----------------
#define NCHUNK 64
__global__ void k3_context(const float* __restrict__ enc,
                           const float* __restrict__ wts,
                           const int* __restrict__ lens,
                           float* __restrict__ ctx) {
    int b = blockIdx.y;
    int len = lens[b];
    int s0 = blockIdx.x * (S_LEN / NCHUNK);
    int s1 = min(s0 + (S_LEN / NCHUNK), len);
    if (s0 >= s1) return;
    int h = threadIdx.x * 4;
    float4 acc = make_float4(0.f, 0.f, 0.f, 0.f);
    for (int s = s0; s < s1; s++) {
        float w = __ldg(&wts[(size_t)b * S_LEN + s]);
        float4 e = *(const float4*)(enc + ((size_t)(s * B_DIM + b)) * H_DIM + h);
        acc.x += w * e.x; acc.y += w * e.y; acc.z += w * e.z; acc.w += w * e.w;
    }
    float* c = ctx + (size_t)b * H_DIM + h;
    atomicAdd(c + 0, acc.x);
    atomicAdd(c + 1, acc.y);
    atomicAdd(c + 2, acc.z);
    atomicAdd(c + 3, acc.w);
}

// ---------------- launcher ----------------
extern "C" void kernel_launch(void* const* d_in, const int* in_sizes, int n_in,
                              void* d_out, int out_size) {
    const float* hidden = (const float*)d_in[0];
    const float* enc    = (const float*)d_in[1];
    const int*   lens   = (const int*)d_in[2];
    const float* attn_w = (const float*)d_in[3];
    const float* attn_b = (const float*)d_in[4];
    const float* v      = (const float*)d_in[5];

    float* out = (float*)d_out;
    float* ctx = out;
    float* wts = out + B_DIM * H_DIM;

    cudaFuncSetAttribute(k1_gemm, cudaFuncAttributeMaxDynamicSharedMemorySize, K1_SMEM);

    k_prep<<<PREP_GRID, 256>>>((const float4*)enc, attn_w, attn_b, hidden, lens, ctx);
    dim3 g1(H_DIM / BN, M_TOT / BM);     // (8, 512); CTAs beyond g_total exit early
    k1_gemm<<<g1, 128, K1_SMEM>>>(v);
    k2_softmax<<<B_DIM, 256>>>(lens, wts);
    dim3 g3(NCHUNK, B_DIM);
    k3_context<<<g3, 256>>>(enc, wts, lens, ctx);
}